// round 4
// baseline (speedup 1.0000x reference)
#include <cuda_runtime.h>

// LSTM (relu activations, forget_bias=1) + per-timestep dense.
// B=64, T=512, I=128, H=1024, O=128. Gate order in Wk columns: i, j, f, o.
//
// Structure:
//   init_state:   zero h0/c0 (must run inside the graph for replay determinism)
//   lstm_step x512: z = [x_t, h] @ Wk (+bias in epilogue) -> gates -> c,h update
//                   one kernel per step; kernel boundary = device-wide sync
//   dense_kernel: out = Hout @ Wd + bd

#define Bsz  64
#define Tlen 512
#define Isz  128
#define Hsz  1024
#define KTOT (Isz + Hsz)   /* 1152 */
#define G4   (4 * Hsz)     /* 4096 */
#define Osz  128
#define KC   64

// Scratch state (device globals: allocation-free per harness rules)
__device__ float g_h[2][Bsz * Hsz];                    // ping-pong hidden state
__device__ float g_c[Bsz * Hsz];                       // cell state (in-place safe: block-local)
__device__ float g_hout[(size_t)Bsz * Tlen * Hsz];     // full hidden history, 128 MB

__global__ void init_state() {
    int idx = blockIdx.x * blockDim.x + threadIdx.x;
    if (idx < Bsz * Hsz) { g_h[0][idx] = 0.0f; g_c[idx] = 0.0f; }
}

__device__ __forceinline__ float sigf(float x) { return 1.0f / (1.0f + __expf(-x)); }

// One timestep. Grid: 128 blocks, each owns 8 hidden units (32 z-columns =
// 4 gates x 8 units) for all 64 batch rows. 256 threads, thread tile 4 rows x 2 cols.
__global__ __launch_bounds__(256) void lstm_step(
    const float* __restrict__ X, const float* __restrict__ Wk,
    const float* __restrict__ bias, int t)
{
    __shared__ float in_s[64][KC + 1];   // [row][k], +1 pad: conflict-free
    __shared__ float w_s[KC][33];        // [k][col], +1 pad

    const float* h_prev = g_h[t & 1];
    float*       h_next = g_h[(t + 1) & 1];

    const int n0  = blockIdx.x * 8;      // first hidden unit of this block
    const int tid = threadIdx.x;
    const int ty  = tid >> 4;            // 0..15 -> rows ty*4 .. +3
    const int tx  = tid & 15;            // 0..15 -> cols tx*2 .. +1
    const int r0  = ty * 4;
    const int c0  = tx * 2;

    float acc[4][2] = {};

    for (int k0 = 0; k0 < KTOT; k0 += KC) {
        // Input tile [64 rows][KC]: k<128 from X[:,t,:], k>=128 from h_prev.
        // (KC=64 divides I=128 -> each chunk is purely X or purely h.)
        #pragma unroll
        for (int i = 0; i < 16; ++i) {
            int e = i * 256 + tid;
            int r = e >> 6;
            int k = e & 63;
            int kk = k0 + k;
            float v;
            if (kk < Isz) v = X[((size_t)r * Tlen + t) * Isz + kk];
            else          v = h_prev[r * Hsz + (kk - Isz)];
            in_s[r][k] = v;
        }
        // Weight tile [KC][32 cols]; col c -> global column (c/8)*H + n0 + (c%8)
        #pragma unroll
        for (int i = 0; i < 8; ++i) {
            int e = i * 256 + tid;
            int k = e >> 5;
            int c = e & 31;
            int gcol = (c >> 3) * Hsz + n0 + (c & 7);
            w_s[k][c] = Wk[(size_t)(k0 + k) * G4 + gcol];
        }
        __syncthreads();

        #pragma unroll 8
        for (int k = 0; k < KC; ++k) {
            float w0 = w_s[k][c0];
            float w1 = w_s[k][c0 + 1];
            float a0 = in_s[r0    ][k];
            float a1 = in_s[r0 + 1][k];
            float a2 = in_s[r0 + 2][k];
            float a3 = in_s[r0 + 3][k];
            acc[0][0] += a0 * w0;  acc[0][1] += a0 * w1;
            acc[1][0] += a1 * w0;  acc[1][1] += a1 * w1;
            acc[2][0] += a2 * w0;  acc[2][1] += a2 * w1;
            acc[3][0] += a3 * w0;  acc[3][1] += a3 * w1;
        }
        __syncthreads();
    }

    // Stage z into shared (reuse in_s; cols 0..31 within the [.. ][65] stride)
    #pragma unroll
    for (int i = 0; i < 4; ++i) {
        in_s[r0 + i][c0]     = acc[i][0];
        in_s[r0 + i][c0 + 1] = acc[i][1];
    }
    __syncthreads();

    // Epilogue: thread -> (unit u, 2 batch rows). Gate order i, j, f, o.
    const int u  = tid & 7;
    const int rp = tid >> 3;   // 0..31
    const int n  = n0 + u;
    const float bi = bias[n];
    const float bj = bias[Hsz + n];
    const float bf = bias[2 * Hsz + n] + 1.0f;   // TF forget_bias = 1
    const float bo = bias[3 * Hsz + n];

    #pragma unroll
    for (int s = 0; s < 2; ++s) {
        int r = rp * 2 + s;
        float zi = in_s[r][u]      + bi;
        float zj = in_s[r][8 + u]  + bj;
        float zf = in_s[r][16 + u] + bf;
        float zo = in_s[r][24 + u] + bo;
        float ig = sigf(zi);
        float gg = fmaxf(zj, 0.0f);        // relu cell-input activation
        float fg = sigf(zf);
        float og = sigf(zo);
        int idx = r * Hsz + n;
        float cn = fg * g_c[idx] + ig * gg;
        g_c[idx] = cn;
        float hn = og * fmaxf(cn, 0.0f);   // relu output activation
        h_next[idx] = hn;
        g_hout[((size_t)r * Tlen + t) * Hsz + n] = hn;
    }
}

// out[M=B*T][O=128] = g_hout[M][H] @ Wd + bd
// Block tile 64 rows x 32 cols, 256 threads, thread tile 4x2.
__global__ __launch_bounds__(256) void dense_kernel(
    const float* __restrict__ Wd, const float* __restrict__ bd,
    float* __restrict__ out)
{
    __shared__ float in_s[64][KC + 1];
    __shared__ float w_s[KC][33];

    const int row0 = blockIdx.x * 64;
    const int col0 = blockIdx.y * 32;
    const int tid  = threadIdx.x;
    const int ty   = tid >> 4;
    const int tx   = tid & 15;
    const int r0   = ty * 4;
    const int c0   = tx * 2;

    float acc[4][2] = {};

    for (int k0 = 0; k0 < Hsz; k0 += KC) {
        #pragma unroll
        for (int i = 0; i < 16; ++i) {
            int e = i * 256 + tid;
            int r = e >> 6;
            int k = e & 63;
            in_s[r][k] = g_hout[(size_t)(row0 + r) * Hsz + k0 + k];
        }
        #pragma unroll
        for (int i = 0; i < 8; ++i) {
            int e = i * 256 + tid;
            int k = e >> 5;
            int c = e & 31;
            w_s[k][c] = Wd[(size_t)(k0 + k) * Osz + col0 + c];
        }
        __syncthreads();

        #pragma unroll 8
        for (int k = 0; k < KC; ++k) {
            float w0 = w_s[k][c0], w1 = w_s[k][c0 + 1];
            float a0 = in_s[r0    ][k];
            float a1 = in_s[r0 + 1][k];
            float a2 = in_s[r0 + 2][k];
            float a3 = in_s[r0 + 3][k];
            acc[0][0] += a0 * w0;  acc[0][1] += a0 * w1;
            acc[1][0] += a1 * w0;  acc[1][1] += a1 * w1;
            acc[2][0] += a2 * w0;  acc[2][1] += a2 * w1;
            acc[3][0] += a3 * w0;  acc[3][1] += a3 * w1;
        }
        __syncthreads();
    }

    float b0 = bd[col0 + c0];
    float b1 = bd[col0 + c0 + 1];
    #pragma unroll
    for (int i = 0; i < 4; ++i) {
        out[(size_t)(row0 + r0 + i) * Osz + col0 + c0]     = acc[i][0] + b0;
        out[(size_t)(row0 + r0 + i) * Osz + col0 + c0 + 1] = acc[i][1] + b1;
    }
}

extern "C" void kernel_launch(void* const* d_in, const int* in_sizes, int n_in,
                              void* d_out, int out_size)
{
    const float* X  = (const float*)d_in[0];   // [B, T, I]
    const float* Wk = (const float*)d_in[1];   // [I+H, 4H]
    const float* b  = (const float*)d_in[2];   // [4H]
    const float* Wd = (const float*)d_in[3];   // [H, O]
    const float* bd = (const float*)d_in[4];   // [O]
    float* out = (float*)d_out;                // [B, T, O]

    (void)in_sizes; (void)n_in; (void)out_size;

    init_state<<<(Bsz * Hsz + 255) / 256, 256>>>();

    for (int t = 0; t < Tlen; ++t)
        lstm_step<<<128, 256>>>(X, Wk, b, t);

    dim3 dgrid(Bsz * Tlen / 64, Osz / 32);
    dense_kernel<<<dgrid, 256>>>(Wd, bd, out);
}

// round 6
// speedup vs baseline: 1.5373x; 1.5373x over previous
#include <cuda_runtime.h>

// LSTM (relu activations, forget_bias=1) + per-timestep dense.
// B=64, T=512, I=128, H=1024, O=128. Gate order in Wk columns: i, j, f, o.
//
// Graph has exactly 3 nodes (R4 failed the teardown rule at 1027 nodes):
//   init_state      : zero h0 and the grid-barrier counter
//   lstm_persistent : ALL 512 timesteps in one launch; software grid barrier
//                     between the K-split GEMM phase and the gate/update phase
//   dense_kernel    : out = Hout @ Wd + bd

#define Bsz   64
#define Tlen  512
#define Isz   128
#define Hsz   1024
#define KTOT  1152
#define G4    4096
#define Osz   128

#define NBLK  144          // 16 col-tiles x 9 K-splits; <= 148 SMs -> co-resident
#define KSPL  9
#define KSL   128          // K per split (split 0 = pure X, splits 1..8 = pure h)
#define KC    32
#define CTILE 256          // z-columns per block

// Device-global scratch (allocation-free per harness rules)
__device__ float    g_h[Bsz * Hsz];                      // hidden state (single buffer)
__device__ float    g_zp[KSPL][Bsz * G4];                // K-split partials (9.4 MB)
__device__ float    g_hout[(size_t)Bsz * Tlen * Hsz];    // hidden history (128 MB)
__device__ unsigned g_bar;                               // grid-barrier counter

__global__ void init_state() {
    int idx = blockIdx.x * blockDim.x + threadIdx.x;
    if (idx < Bsz * Hsz) g_h[idx] = 0.0f;
    if (idx == 0) g_bar = 0u;
}

__device__ __forceinline__ float sigf(float x) { return 1.0f / (1.0f + __expf(-x)); }

// Software grid barrier. All NBLK blocks are co-resident (144 <= 148 SMs,
// 1 small block per SM), so spinning is safe. Counter monotonically increases;
// reset by init_state on every graph replay.
__device__ __forceinline__ void grid_sync(unsigned& target) {
    __threadfence();                       // publish this thread's stores (cumulative)
    __syncthreads();
    target += NBLK;
    if (threadIdx.x == 0) {
        atomicAdd(&g_bar, 1u);
        while (*(volatile unsigned*)&g_bar < target) { }
    }
    __syncthreads();
}

// ---------------------------------------------------------------------------
// Persistent kernel: 144 blocks x 256 threads, loops over all 512 timesteps.
// Phase A: partial GEMM  z_part = [x_t, h] (K-slice) @ Wk (col-slice)
//          block tile 64 x 256, thread tile 8 x 8 -> 64 FFMA per k-iter.
// Phase B: blocks 0..127 reduce 9 partials + bias -> gates -> c (registers!) ,
//          h (global), hout. h/partials read via __ldcg (L1 not coherent).
// ---------------------------------------------------------------------------
__global__ __launch_bounds__(256, 1) void lstm_persistent(
    const float* __restrict__ X, const float* __restrict__ Wk,
    const float* __restrict__ bias)
{
    __shared__ float a_s[64][KC + 1];    // [batch row][k]
    __shared__ float w_s[KC][CTILE];     // [k][col]

    const int bid = blockIdx.x;
    const int col = bid / KSPL;          // 0..15  -> z-cols [col*256, +256)
    const int ks  = bid - col * KSPL;    // 0..8   -> k in [ks*128, +128)
    const int cb  = col * CTILE;
    const int kb  = ks * KSL;

    const int tid = threadIdx.x;
    const int ty  = tid >> 5;            // warp id 0..7 -> rows ty*8..+7
    const int tx  = tid & 31;            // lane -> cols tx*8..+7
    const int r0  = ty * 8;
    const int c0  = tx * 8;

    // Phase-B ownership: blocks 0..127 each own 512 of the 65536 (b,n) elems.
    const bool upd = (bid < 128);
    float creg[2] = {0.0f, 0.0f};        // cell state lives in registers all 512 steps
    int   uidx[2];
    if (upd) {
        uidx[0] = bid * 512 + tid;       // e=0
        uidx[1] = bid * 512 + 256 + tid; // e=1  (consecutive tid -> consecutive n)
    }

    unsigned bar_target = 0;
    float* __restrict__ zp = g_zp[ks];

    for (int t = 0; t < Tlen; ++t) {
        // ---- Phase A: partial GEMM over this block's K-slice ----
        float acc[8][8] = {};

        #pragma unroll
        for (int kc = 0; kc < KSL; kc += KC) {
            const int kkb = kb + kc;
            // a_s[64][32]: 8 rows per thread-group, coalesced over k
            if (ks == 0) {               // pure X slice (k < 128)
                #pragma unroll
                for (int i = 0; i < 8; ++i) {
                    int r = i * 8 + ty;
                    a_s[r][tx] = X[((size_t)r * Tlen + t) * Isz + kkb + tx];
                }
            } else {                     // pure h slice
                #pragma unroll
                for (int i = 0; i < 8; ++i) {
                    int r = i * 8 + ty;
                    a_s[r][tx] = __ldcg(&g_h[r * Hsz + (kkb - Isz) + tx]);
                }
            }
            // w_s[32][256]: 8 float4 per thread, coalesced over cols
            #pragma unroll
            for (int i = 0; i < 8; ++i) {
                int idx = i * 256 + tid;
                int k   = idx >> 6;
                int c4  = idx & 63;
                ((float4*)&w_s[k][0])[c4] =
                    *(const float4*)&Wk[(size_t)(kkb + k) * G4 + cb + c4 * 4];
            }
            __syncthreads();

            #pragma unroll
            for (int k = 0; k < KC; ++k) {
                float4 w0 = *(const float4*)&w_s[k][c0];
                float4 w1 = *(const float4*)&w_s[k][c0 + 4];
                #pragma unroll
                for (int i = 0; i < 8; ++i) {
                    float a = a_s[r0 + i][k];              // warp-broadcast LDS
                    acc[i][0] += a * w0.x;  acc[i][1] += a * w0.y;
                    acc[i][2] += a * w0.z;  acc[i][3] += a * w0.w;
                    acc[i][4] += a * w1.x;  acc[i][5] += a * w1.y;
                    acc[i][6] += a * w1.z;  acc[i][7] += a * w1.w;
                }
            }
            __syncthreads();
        }

        // write partials (own split's buffer; fully overwritten every step)
        #pragma unroll
        for (int i = 0; i < 8; ++i) {
            float4 o0, o1;
            o0.x = acc[i][0]; o0.y = acc[i][1]; o0.z = acc[i][2]; o0.w = acc[i][3];
            o1.x = acc[i][4]; o1.y = acc[i][5]; o1.z = acc[i][6]; o1.w = acc[i][7];
            size_t base = (size_t)(r0 + i) * G4 + cb + c0;
            *(float4*)&zp[base]     = o0;
            *(float4*)&zp[base + 4] = o1;
        }

        grid_sync(bar_target);   // partials visible to everyone

        // ---- Phase B: reduce partials -> gates -> c/h update ----
        if (upd) {
            #pragma unroll
            for (int e = 0; e < 2; ++e) {
                int idx = uidx[e];
                int b = idx >> 10;
                int n = idx & 1023;
                int zrow = b * G4 + n;

                float z[4];
                #pragma unroll
                for (int g = 0; g < 4; ++g) {
                    float v = bias[g * Hsz + n];
                    #pragma unroll
                    for (int s = 0; s < KSPL; ++s)
                        v += __ldcg(&g_zp[s][zrow + g * Hsz]);
                    z[g] = v;
                }

                float ig = sigf(z[0]);
                float gg = fmaxf(z[1], 0.0f);        // relu cell-input activation
                float fg = sigf(z[2] + 1.0f);        // TF forget_bias = 1
                float og = sigf(z[3]);

                float cn = fg * creg[e] + ig * gg;
                creg[e] = cn;
                float hn = og * fmaxf(cn, 0.0f);     // relu output activation
                g_h[idx] = hn;
                g_hout[((size_t)b * Tlen + t) * Hsz + n] = hn;
            }
        }

        grid_sync(bar_target);   // h visible before next step's GEMM reads it
    }
}

// ---------------------------------------------------------------------------
// Final dense: out[B*T][128] = g_hout @ Wd + bd.
// Block tile 64 x 128, 256 threads, thread tile 8x4. grid = (1, 512).
// ---------------------------------------------------------------------------
__global__ __launch_bounds__(256) void dense_kernel(
    const float* __restrict__ Wd, const float* __restrict__ bd,
    float* __restrict__ out)
{
    __shared__ float a_s[64][KC + 1];
    __shared__ float w_s[KC][128];

    const int rb  = blockIdx.y * 64;
    const int tid = threadIdx.x;
    const int ty  = tid >> 5;
    const int tx  = tid & 31;
    const int r0  = ty * 8;
    const int c0  = tx * 4;

    float acc[8][4] = {};

    for (int k0 = 0; k0 < Hsz; k0 += KC) {
        #pragma unroll
        for (int i = 0; i < 8; ++i)
            a_s[i * 8 + ty][tx] = g_hout[(size_t)(rb + i * 8 + ty) * Hsz + k0 + tx];
        #pragma unroll
        for (int i = 0; i < 16; ++i) {
            int k = i * 2 + (tid >> 7);
            int c = tid & 127;
            w_s[k][c] = Wd[(size_t)(k0 + k) * Osz + c];
        }
        __syncthreads();

        #pragma unroll
        for (int k = 0; k < KC; ++k) {
            float4 w = *(const float4*)&w_s[k][c0];
            #pragma unroll
            for (int i = 0; i < 8; ++i) {
                float a = a_s[r0 + i][k];
                acc[i][0] += a * w.x;  acc[i][1] += a * w.y;
                acc[i][2] += a * w.z;  acc[i][3] += a * w.w;
            }
        }
        __syncthreads();
    }

    float4 bv = *(const float4*)&bd[c0];
    #pragma unroll
    for (int i = 0; i < 8; ++i) {
        float4 o;
        o.x = acc[i][0] + bv.x;  o.y = acc[i][1] + bv.y;
        o.z = acc[i][2] + bv.z;  o.w = acc[i][3] + bv.w;
        *(float4*)&out[(size_t)(rb + r0 + i) * Osz + c0] = o;
    }
}

extern "C" void kernel_launch(void* const* d_in, const int* in_sizes, int n_in,
                              void* d_out, int out_size)
{
    const float* X  = (const float*)d_in[0];   // [B, T, I]
    const float* Wk = (const float*)d_in[1];   // [I+H, 4H]
    const float* b  = (const float*)d_in[2];   // [4H]
    const float* Wd = (const float*)d_in[3];   // [H, O]
    const float* bd = (const float*)d_in[4];   // [O]
    float* out = (float*)d_out;                // [B, T, O]
    (void)in_sizes; (void)n_in; (void)out_size;

    init_state<<<(Bsz * Hsz + 255) / 256, 256>>>();
    lstm_persistent<<<NBLK, 256>>>(X, Wk, b);
    dense_kernel<<<dim3(1, (Bsz * Tlen) / 64), 256>>>(Wd, bd, out);
}

// round 7
// speedup vs baseline: 3.9798x; 2.5889x over previous
#include <cuda_runtime.h>
#include <cuda_bf16.h>
#include <cstdint>

// LSTM (relu activations, forget_bias=1) + per-timestep dense.
// B=64, T=512, I=128, H=1024, O=128. Gate order in Wk columns: i, j, f, o.
//
// Graph: 5 nodes.
//   prep_w  : Wk -> transposed bf16 hi/lo planes  WkT[n][k]   (one-time)
//   prep_x  : X  -> bf16 hi/lo planes (same layout)           (one-time)
//   init    : zero h_hi/h_lo + barrier counter
//   lstm_persistent : all 512 steps. Phase A = K-split tensor-core GEMM
//       (mma.sync m16n8k16 bf16, 3-term hi/lo for ~fp32 accuracy), flush-free
//       grid barrier (red.release / ld.acquire -- NO threadfence, so no
//       CCTL.IVALL L1 flush; weight tiles stay L1-resident all 512 steps).
//       Phase B = partial reduction + gates + c(in registers)/h update.
//   dense   : out = Hout @ Wd + bd  (fp32 FFMA, tiny)

#define Bsz   64
#define Tlen  512
#define Isz   128
#define Hsz   1024
#define KTOT  1152
#define G4    4096
#define Osz   128

#define NBLK  144        // 16 col-tiles x 9 K-splits, co-resident on 148 SMs
#define KSPL  9
#define CTILE 256        // z-columns per block
#define APAD  36         // padded k-stride (bf16 elems) for smem rows

// ---- device-global scratch (allocation-free) ----
__device__ float          g_zp[KSPL][Bsz * G4];                // K-split partials
__device__ __nv_bfloat16  g_h_hi[Bsz * Hsz];
__device__ __nv_bfloat16  g_h_lo[Bsz * Hsz];
__device__ __nv_bfloat16  g_wT_hi[(size_t)G4 * KTOT];          // WkT[n][k] hi
__device__ __nv_bfloat16  g_wT_lo[(size_t)G4 * KTOT];          // WkT[n][k] lo
__device__ __nv_bfloat16  g_x_hi[Bsz * Tlen * Isz];
__device__ __nv_bfloat16  g_x_lo[Bsz * Tlen * Isz];
__device__ float          g_hout[(size_t)Bsz * Tlen * Hsz];    // 128 MB
__device__ unsigned       g_bar;

__device__ __forceinline__ float sigf(float x) { return 1.0f / (1.0f + __expf(-x)); }

// ---------------------------------------------------------------------------
// One-time preprocessing
// ---------------------------------------------------------------------------
__global__ void prep_w(const float* __restrict__ Wk) {
    __shared__ float tile[32][33];
    const int kb0 = blockIdx.x * 32;           // 36 k-tiles
    const int nb0 = blockIdx.y * 32;           // 128 n-tiles
    const int tx = threadIdx.x, ty = threadIdx.y;   // 32 x 8
    #pragma unroll
    for (int i = 0; i < 32; i += 8)
        tile[ty + i][tx] = Wk[(size_t)(kb0 + ty + i) * G4 + nb0 + tx];
    __syncthreads();
    #pragma unroll
    for (int i = 0; i < 32; i += 8) {
        int n = nb0 + ty + i, k = kb0 + tx;
        float v = tile[tx][ty + i];
        __nv_bfloat16 h = __float2bfloat16(v);
        size_t o = (size_t)n * KTOT + k;
        g_wT_hi[o] = h;
        g_wT_lo[o] = __float2bfloat16(v - __bfloat162float(h));
    }
}

__global__ void prep_x(const float* __restrict__ X) {
    int idx = blockIdx.x * 256 + threadIdx.x;     // < B*T*I = 4194304
    float v = X[idx];
    __nv_bfloat16 h = __float2bfloat16(v);
    g_x_hi[idx] = h;
    g_x_lo[idx] = __float2bfloat16(v - __bfloat162float(h));
}

__global__ void init_state() {
    int idx = blockIdx.x * blockDim.x + threadIdx.x;
    if (idx < Bsz * Hsz) {
        g_h_hi[idx] = __float2bfloat16(0.0f);
        g_h_lo[idx] = __float2bfloat16(0.0f);
    }
    if (idx == 0) g_bar = 0u;
}

// ---------------------------------------------------------------------------
// mma.sync m16n8k16 row.col bf16 -> f32
// ---------------------------------------------------------------------------
__device__ __forceinline__ void mma16816(float* d, const uint32_t* a, const uint32_t* b) {
    asm volatile(
        "mma.sync.aligned.m16n8k16.row.col.f32.bf16.bf16.f32 "
        "{%0,%1,%2,%3}, {%4,%5,%6,%7}, {%8,%9}, {%0,%1,%2,%3};"
        : "+f"(d[0]), "+f"(d[1]), "+f"(d[2]), "+f"(d[3])
        : "r"(a[0]), "r"(a[1]), "r"(a[2]), "r"(a[3]), "r"(b[0]), "r"(b[1]));
}

// Flush-free grid barrier: release-arrive + acquire-spin. No membar.gl, so
// ptxas emits NO CCTL.IVALL -> L1 survives across steps. All mutable
// cross-SM data is read via __ldcg (L1-bypass), so this is coherent.
__device__ __forceinline__ void grid_sync(unsigned& target) {
    __syncthreads();
    target += NBLK;
    if (threadIdx.x == 0) {
        asm volatile("red.release.gpu.add.u32 [%0], %1;" :: "l"(&g_bar), "r"(1u) : "memory");
        unsigned v;
        do {
            asm volatile("ld.acquire.gpu.u32 %0, [%1];" : "=r"(v) : "l"(&g_bar) : "memory");
        } while (v < target);
    }
    __syncthreads();
}

// ---------------------------------------------------------------------------
// Persistent kernel: 144 blocks x 256 threads.
// Block (colb, ks): z-cols [colb*256,+256), K-slice [ks*128,+128) of 1152.
// Warp w owns n-subtile [w*32,+32); M=64 full. acc = 4(m) x 4(n) mma tiles.
// ---------------------------------------------------------------------------
__global__ __launch_bounds__(256, 1) void lstm_persistent(const float* __restrict__ bias)
{
    __shared__ __align__(16) uint16_t a_s[2][64 * APAD];      // [plane][row*APAD+k]
    __shared__ __align__(16) uint16_t w_s[2][CTILE * APAD];   // [plane][n*APAD+k]

    const int bid  = blockIdx.x;
    const int colb = bid / KSPL;
    const int ks   = bid - colb * KSPL;
    const int cb   = colb * CTILE;
    const int kb   = ks * 128;          // within 1152 (ks=0 -> X cols)

    const int tid  = threadIdx.x;
    const int w    = tid >> 5;
    const int lane = tid & 31;
    const int gq   = lane >> 2;         // 0..7
    const int qq   = lane & 3;          // 0..3

    // Phase-B ownership: blocks 0..127 each own 512 (b,n) elements.
    const bool upd = (bid < 128);
    float creg[2] = {0.0f, 0.0f};
    int   uidx[2] = {0, 0};
    if (upd) { uidx[0] = bid * 512 + tid; uidx[1] = bid * 512 + 256 + tid; }

    const uint32_t* __restrict__ wThi = (const uint32_t*)g_wT_hi;  // [n][576] words
    const uint32_t* __restrict__ wTlo = (const uint32_t*)g_wT_lo;
    const uint32_t* __restrict__ xhi  = (const uint32_t*)g_x_hi;   // [b][t][64]
    const uint32_t* __restrict__ xlo  = (const uint32_t*)g_x_lo;
    const unsigned* __restrict__ hhi  = (const unsigned*)g_h_hi;   // [b][512]
    const unsigned* __restrict__ hlo  = (const unsigned*)g_h_lo;

    float* __restrict__ zp = g_zp[ks];
    unsigned bar_target = 0;

    for (int t = 0; t < Tlen; ++t) {
        float acc[4][4][4] = {};

        #pragma unroll
        for (int kc = 0; kc < 4; ++kc) {          // 4 x 32-k chunks
            // ---- stage A (64 x 32 bf16, hi+lo) ----
            #pragma unroll
            for (int i = 0; i < 4; ++i) {
                int wi  = i * 256 + tid;          // 0..1023
                int row = wi >> 4;
                int kw  = wi & 15;
                uint32_t vh, vl;
                if (ks == 0) {
                    size_t gidx = ((size_t)row * Tlen + t) * 64 + kc * 16 + kw;
                    vh = xhi[gidx];  vl = xlo[gidx];
                } else {
                    int hword = ((kb - Isz) >> 1) + kc * 16 + kw;
                    vh = __ldcg(hhi + row * 512 + hword);
                    vl = __ldcg(hlo + row * 512 + hword);
                }
                *(uint32_t*)&a_s[0][row * APAD + kw * 2] = vh;
                *(uint32_t*)&a_s[1][row * APAD + kw * 2] = vl;
            }
            // ---- stage W (256 x 32 bf16, hi+lo); immutable -> L1-cached ----
            #pragma unroll
            for (int i = 0; i < 16; ++i) {
                int wi = i * 256 + tid;           // 0..4095
                int n  = wi >> 4;
                int kw = wi & 15;
                size_t gidx = (size_t)(cb + n) * 576 + ((kb + kc * 32) >> 1) + kw;
                *(uint32_t*)&w_s[0][n * APAD + kw * 2] = wThi[gidx];
                *(uint32_t*)&w_s[1][n * APAD + kw * 2] = wTlo[gidx];
            }
            __syncthreads();

            #pragma unroll
            for (int kk = 0; kk < 32; kk += 16) {
                uint32_t bh[4][2], bl[4][2];
                #pragma unroll
                for (int ni = 0; ni < 4; ++ni) {
                    int off = (w * 32 + ni * 8 + gq) * APAD + kk + qq * 2;
                    bh[ni][0] = *(const uint32_t*)&w_s[0][off];
                    bh[ni][1] = *(const uint32_t*)&w_s[0][off + 8];
                    bl[ni][0] = *(const uint32_t*)&w_s[1][off];
                    bl[ni][1] = *(const uint32_t*)&w_s[1][off + 8];
                }
                #pragma unroll
                for (int mi = 0; mi < 4; ++mi) {
                    int o0 = (mi * 16 + gq) * APAD + kk + qq * 2;
                    int o1 = (mi * 16 + gq + 8) * APAD + kk + qq * 2;
                    uint32_t ah[4] = { *(const uint32_t*)&a_s[0][o0],
                                       *(const uint32_t*)&a_s[0][o1],
                                       *(const uint32_t*)&a_s[0][o0 + 8],
                                       *(const uint32_t*)&a_s[0][o1 + 8] };
                    uint32_t al[4] = { *(const uint32_t*)&a_s[1][o0],
                                       *(const uint32_t*)&a_s[1][o1],
                                       *(const uint32_t*)&a_s[1][o0 + 8],
                                       *(const uint32_t*)&a_s[1][o1 + 8] };
                    #pragma unroll
                    for (int ni = 0; ni < 4; ++ni) {
                        mma16816(acc[mi][ni], ah, bh[ni]);   // hi*hi
                        mma16816(acc[mi][ni], ah, bl[ni]);   // hi*lo
                        mma16816(acc[mi][ni], al, bh[ni]);   // lo*hi
                    }
                }
            }
            __syncthreads();
        }

        // ---- write z partials (fp32) ----
        #pragma unroll
        for (int mi = 0; mi < 4; ++mi)
            #pragma unroll
            for (int ni = 0; ni < 4; ++ni) {
                int r   = mi * 16 + gq;
                int col = cb + w * 32 + ni * 8 + qq * 2;
                float2 v0 = make_float2(acc[mi][ni][0], acc[mi][ni][1]);
                float2 v1 = make_float2(acc[mi][ni][2], acc[mi][ni][3]);
                *(float2*)&zp[(size_t)r * G4 + col]       = v0;
                *(float2*)&zp[(size_t)(r + 8) * G4 + col] = v1;
            }

        grid_sync(bar_target);   // partials visible (release/acquire)

        // ---- Phase B: reduce partials -> gates -> c/h ----
        if (upd) {
            #pragma unroll
            for (int e = 0; e < 2; ++e) {
                int idx = uidx[e];
                int b = idx >> 10;
                int n = idx & 1023;
                int zrow = b * G4 + n;

                float z[4];
                #pragma unroll
                for (int g = 0; g < 4; ++g) {
                    float v = bias[g * Hsz + n];
                    #pragma unroll
                    for (int s = 0; s < KSPL; ++s)
                        v += __ldcg(&g_zp[s][zrow + g * Hsz]);
                    z[g] = v;
                }

                float ig = sigf(z[0]);
                float gg = fmaxf(z[1], 0.0f);        // relu cell-input activation
                float fg = sigf(z[2] + 1.0f);        // TF forget_bias = 1
                float og = sigf(z[3]);

                float cn = fg * creg[e] + ig * gg;
                creg[e] = cn;
                float hn = og * fmaxf(cn, 0.0f);     // relu output activation

                __nv_bfloat16 hh = __float2bfloat16(hn);
                g_h_hi[idx] = hh;
                g_h_lo[idx] = __float2bfloat16(hn - __bfloat162float(hh));
                g_hout[((size_t)b * Tlen + t) * Hsz + n] = hn;
            }
        }

        grid_sync(bar_target);   // h visible before next step's GEMM
    }
}

// ---------------------------------------------------------------------------
// Final dense: out[B*T][128] = g_hout @ Wd + bd.  (unchanged from R5)
// ---------------------------------------------------------------------------
#define KC 32
__global__ __launch_bounds__(256) void dense_kernel(
    const float* __restrict__ Wd, const float* __restrict__ bd,
    float* __restrict__ out)
{
    __shared__ float a_s[64][KC + 1];
    __shared__ float w_s[KC][128];

    const int rb  = blockIdx.y * 64;
    const int tid = threadIdx.x;
    const int ty  = tid >> 5;
    const int tx  = tid & 31;
    const int r0  = ty * 8;
    const int c0  = tx * 4;

    float acc[8][4] = {};

    for (int k0 = 0; k0 < Hsz; k0 += KC) {
        #pragma unroll
        for (int i = 0; i < 8; ++i)
            a_s[i * 8 + ty][tx] = g_hout[(size_t)(rb + i * 8 + ty) * Hsz + k0 + tx];
        #pragma unroll
        for (int i = 0; i < 16; ++i) {
            int k = i * 2 + (tid >> 7);
            int c = tid & 127;
            w_s[k][c] = Wd[(size_t)(k0 + k) * Osz + c];
        }
        __syncthreads();

        #pragma unroll
        for (int k = 0; k < KC; ++k) {
            float4 wv = *(const float4*)&w_s[k][c0];
            #pragma unroll
            for (int i = 0; i < 8; ++i) {
                float a = a_s[r0 + i][k];
                acc[i][0] += a * wv.x;  acc[i][1] += a * wv.y;
                acc[i][2] += a * wv.z;  acc[i][3] += a * wv.w;
            }
        }
        __syncthreads();
    }

    float4 bv = *(const float4*)&bd[c0];
    #pragma unroll
    for (int i = 0; i < 8; ++i) {
        float4 o;
        o.x = acc[i][0] + bv.x;  o.y = acc[i][1] + bv.y;
        o.z = acc[i][2] + bv.z;  o.w = acc[i][3] + bv.w;
        *(float4*)&out[(size_t)(rb + r0 + i) * Osz + c0] = o;
    }
}

extern "C" void kernel_launch(void* const* d_in, const int* in_sizes, int n_in,
                              void* d_out, int out_size)
{
    const float* X  = (const float*)d_in[0];   // [B, T, I]
    const float* Wk = (const float*)d_in[1];   // [I+H, 4H]
    const float* b  = (const float*)d_in[2];   // [4H]
    const float* Wd = (const float*)d_in[3];   // [H, O]
    const float* bd = (const float*)d_in[4];   // [O]
    float* out = (float*)d_out;                // [B, T, O]
    (void)in_sizes; (void)n_in; (void)out_size;

    prep_w<<<dim3(KTOT / 32, G4 / 32), dim3(32, 8)>>>(Wk);
    prep_x<<<(Bsz * Tlen * Isz) / 256, 256>>>(X);
    init_state<<<(Bsz * Hsz + 255) / 256, 256>>>();
    lstm_persistent<<<NBLK, 256>>>(b);
    dense_kernel<<<dim3(1, (Bsz * Tlen) / 64), 256>>>(Wd, bd, out);
}

// round 8
// speedup vs baseline: 5.5942x; 1.4056x over previous
#include <cuda_runtime.h>
#include <cuda_bf16.h>
#include <cstdint>

// LSTM (relu activations, forget_bias=1) + per-timestep dense.
// B=64, T=512, I=128, H=1024, O=128. Gate order in Wk columns: i, j, f, o.
//
// Graph: 5 nodes. The persistent kernel now keeps its weight slice resident
// in 170 KB of dynamic shared memory for all 512 steps (R6 re-staged 128 KB
// of immutable weights from global every step -> L1 was 52% busy).
//
//   prep_w  : Wk -> transposed bf16 hi/lo planes WkT[n][k]  (one-time)
//   prep_x  : X  -> bf16 hi/lo planes                        (one-time)
//   init    : zero h planes + barrier counter
//   lstm_persistent : all 512 steps; tensor-core GEMM (m16n8k16 bf16 x3
//       hi/lo terms), flush-free grid barrier (red.release/ld.acquire,
//       no CCTL.IVALL), cell state in registers.
//   dense   : out = Hout @ Wd + bd

#define Bsz   64
#define Tlen  512
#define Isz   128
#define Hsz   1024
#define KTOT  1152
#define G4    4096
#define Osz   128

#define NBLK  144        // 16 col-tiles x 9 K-splits, co-resident on 148 SMs
#define KSPL  9
#define CTILE 256        // z-columns per block
#define KP    136        // padded k-stride (bf16) -> conflict-free fragments
#define W_PLANE (CTILE * KP)   /* 34816 elems */
#define A_PLANE (64 * KP)      /* 8704 elems  */
#define SMEM_BYTES ((2 * W_PLANE + 2 * A_PLANE) * 2)   /* 174080 B */

// ---- device-global scratch (allocation-free) ----
__device__ float          g_zp[KSPL][Bsz * G4];                // K-split partials
__device__ __nv_bfloat16  g_h_hi[Bsz * Hsz];
__device__ __nv_bfloat16  g_h_lo[Bsz * Hsz];
__device__ __nv_bfloat16  g_wT_hi[(size_t)G4 * KTOT];          // WkT[n][k] hi
__device__ __nv_bfloat16  g_wT_lo[(size_t)G4 * KTOT];          // WkT[n][k] lo
__device__ __nv_bfloat16  g_x_hi[Bsz * Tlen * Isz];
__device__ __nv_bfloat16  g_x_lo[Bsz * Tlen * Isz];
__device__ float          g_hout[(size_t)Bsz * Tlen * Hsz];    // 128 MB
__device__ unsigned       g_bar;

__device__ __forceinline__ float sigf(float x) { return 1.0f / (1.0f + __expf(-x)); }

// ---------------------------------------------------------------------------
// One-time preprocessing
// ---------------------------------------------------------------------------
__global__ void prep_w(const float* __restrict__ Wk) {
    __shared__ float tile[32][33];
    const int kb0 = blockIdx.x * 32;
    const int nb0 = blockIdx.y * 32;
    const int tx = threadIdx.x, ty = threadIdx.y;   // 32 x 8
    #pragma unroll
    for (int i = 0; i < 32; i += 8)
        tile[ty + i][tx] = Wk[(size_t)(kb0 + ty + i) * G4 + nb0 + tx];
    __syncthreads();
    #pragma unroll
    for (int i = 0; i < 32; i += 8) {
        int n = nb0 + ty + i, k = kb0 + tx;
        float v = tile[tx][ty + i];
        __nv_bfloat16 h = __float2bfloat16(v);
        size_t o = (size_t)n * KTOT + k;
        g_wT_hi[o] = h;
        g_wT_lo[o] = __float2bfloat16(v - __bfloat162float(h));
    }
}

__global__ void prep_x(const float* __restrict__ X) {
    int idx = blockIdx.x * 256 + threadIdx.x;
    float v = X[idx];
    __nv_bfloat16 h = __float2bfloat16(v);
    g_x_hi[idx] = h;
    g_x_lo[idx] = __float2bfloat16(v - __bfloat162float(h));
}

__global__ void init_state() {
    int idx = blockIdx.x * blockDim.x + threadIdx.x;
    if (idx < Bsz * Hsz) {
        g_h_hi[idx] = __float2bfloat16(0.0f);
        g_h_lo[idx] = __float2bfloat16(0.0f);
    }
    if (idx == 0) g_bar = 0u;
}

__device__ __forceinline__ void mma16816(float* d, const uint32_t* a, const uint32_t* b) {
    asm volatile(
        "mma.sync.aligned.m16n8k16.row.col.f32.bf16.bf16.f32 "
        "{%0,%1,%2,%3}, {%4,%5,%6,%7}, {%8,%9}, {%0,%1,%2,%3};"
        : "+f"(d[0]), "+f"(d[1]), "+f"(d[2]), "+f"(d[3])
        : "r"(a[0]), "r"(a[1]), "r"(a[2]), "r"(a[3]), "r"(b[0]), "r"(b[1]));
}

// Flush-free grid barrier (no membar.gl -> no CCTL.IVALL L1 flush).
// Mutable cross-SM data is read via __ldcg, so this stays coherent.
__device__ __forceinline__ void grid_sync(unsigned& target) {
    __syncthreads();
    target += NBLK;
    if (threadIdx.x == 0) {
        asm volatile("red.release.gpu.add.u32 [%0], %1;" :: "l"(&g_bar), "r"(1u) : "memory");
        unsigned v;
        do {
            asm volatile("ld.acquire.gpu.u32 %0, [%1];" : "=r"(v) : "l"(&g_bar) : "memory");
        } while (v < target);
    }
    __syncthreads();
}

// ---------------------------------------------------------------------------
// Persistent kernel: 144 blocks x 256 threads, 170 KB dynamic smem.
// Block (colb, ks): z-cols [colb*256,+256), K-slice [ks*128,+128) of 1152.
// Weights (hi+lo) for this slice live in smem across ALL 512 steps.
// ---------------------------------------------------------------------------
__global__ __launch_bounds__(256, 1) void lstm_persistent(const float* __restrict__ bias)
{
    extern __shared__ __align__(16) uint16_t sm[];
    uint16_t* __restrict__ w_sm = sm;                  // [plane][n][KP]
    uint16_t* __restrict__ a_sm = sm + 2 * W_PLANE;    // [plane][row][KP]

    const int bid  = blockIdx.x;
    const int colb = bid / KSPL;
    const int ks   = bid - colb * KSPL;
    const int cb   = colb * CTILE;
    const int kb   = ks * 128;          // within 1152 (ks=0 -> X slice)

    const int tid  = threadIdx.x;
    const int w    = tid >> 5;
    const int lane = tid & 31;
    const int gq   = lane >> 2;         // 0..7
    const int qq   = lane & 3;          // 0..3

    // ---- one-time: load this block's weight slice into smem (hi+lo) ----
    {
        const uint4* __restrict__ whi = (const uint4*)g_wT_hi;   // [n][144] uint4
        const uint4* __restrict__ wlo = (const uint4*)g_wT_lo;
        #pragma unroll
        for (int i = 0; i < 32; ++i) {
            int idx   = i * 256 + tid;          // 0..8191
            int plane = idx >> 12;
            int rem   = idx & 4095;
            int n     = rem >> 4;
            int kq    = rem & 15;
            const uint4* src = plane ? wlo : whi;
            uint4 v = src[(size_t)(cb + n) * 144 + (kb >> 3) + kq];
            *(uint4*)&w_sm[plane * W_PLANE + n * KP + kq * 8] = v;
        }
    }

    // Phase-B ownership: blocks 0..127 each own 512 (b,n) elements.
    const bool upd = (bid < 128);
    float creg[2] = {0.0f, 0.0f};
    int   uidx[2] = {0, 0};
    float zb[2][4];
    if (upd) {
        uidx[0] = bid * 512 + tid;
        uidx[1] = bid * 512 + 256 + tid;
        #pragma unroll
        for (int e = 0; e < 2; ++e) {
            int n = uidx[e] & 1023;
            zb[e][0] = bias[n];
            zb[e][1] = bias[Hsz + n];
            zb[e][2] = bias[2 * Hsz + n] + 1.0f;   // TF forget_bias = 1
            zb[e][3] = bias[3 * Hsz + n];
        }
    }

    const uint4* __restrict__ xhi = (const uint4*)g_x_hi;   // [(b*T+t)][16]
    const uint4* __restrict__ xlo = (const uint4*)g_x_lo;
    const uint4* __restrict__ hhi = (const uint4*)g_h_hi;   // [b][128]
    const uint4* __restrict__ hlo = (const uint4*)g_h_lo;

    float* __restrict__ zp = g_zp[ks];
    unsigned bar_target = 0;

    for (int t = 0; t < Tlen; ++t) {
        // ---- stage A tile (64 rows x 128 k, hi+lo planes) ----
        #pragma unroll
        for (int i = 0; i < 8; ++i) {
            int idx   = i * 256 + tid;          // 0..2047
            int plane = idx >> 10;
            int rem   = idx & 1023;
            int row   = rem >> 4;
            int kq    = rem & 15;
            uint4 v;
            if (ks == 0) {
                const uint4* src = plane ? xlo : xhi;
                v = src[((size_t)row * Tlen + t) * 16 + kq];
            } else {
                const uint4* src = plane ? hlo : hhi;
                v = __ldcg(&src[(size_t)row * 128 + ((kb - Isz) >> 3) + kq]);
            }
            *(uint4*)&a_sm[plane * A_PLANE + row * KP + kq * 8] = v;
        }
        __syncthreads();

        // ---- MMA: 64 x 256 x 128, 3 hi/lo terms ----
        float acc[4][4][4] = {};
        #pragma unroll
        for (int kk = 0; kk < 128; kk += 16) {
            uint32_t bh[4][2], bl[4][2];
            #pragma unroll
            for (int ni = 0; ni < 4; ++ni) {
                int off = (w * 32 + ni * 8 + gq) * KP + kk + qq * 2;
                bh[ni][0] = *(const uint32_t*)&w_sm[off];
                bh[ni][1] = *(const uint32_t*)&w_sm[off + 8];
                bl[ni][0] = *(const uint32_t*)&w_sm[W_PLANE + off];
                bl[ni][1] = *(const uint32_t*)&w_sm[W_PLANE + off + 8];
            }
            #pragma unroll
            for (int mi = 0; mi < 4; ++mi) {
                int o0 = (mi * 16 + gq) * KP + kk + qq * 2;
                int o1 = o0 + 8 * KP;
                uint32_t ah[4] = { *(const uint32_t*)&a_sm[o0],
                                   *(const uint32_t*)&a_sm[o1],
                                   *(const uint32_t*)&a_sm[o0 + 8],
                                   *(const uint32_t*)&a_sm[o1 + 8] };
                uint32_t al[4] = { *(const uint32_t*)&a_sm[A_PLANE + o0],
                                   *(const uint32_t*)&a_sm[A_PLANE + o1],
                                   *(const uint32_t*)&a_sm[A_PLANE + o0 + 8],
                                   *(const uint32_t*)&a_sm[A_PLANE + o1 + 8] };
                #pragma unroll
                for (int ni = 0; ni < 4; ++ni) {
                    mma16816(acc[mi][ni], ah, bh[ni]);   // hi*hi
                    mma16816(acc[mi][ni], ah, bl[ni]);   // hi*lo
                    mma16816(acc[mi][ni], al, bh[ni]);   // lo*hi
                }
            }
        }

        // ---- write z partials ----
        #pragma unroll
        for (int mi = 0; mi < 4; ++mi)
            #pragma unroll
            for (int ni = 0; ni < 4; ++ni) {
                int r   = mi * 16 + gq;
                int col = cb + w * 32 + ni * 8 + qq * 2;
                *(float2*)&zp[(size_t)r * G4 + col] =
                    make_float2(acc[mi][ni][0], acc[mi][ni][1]);
                *(float2*)&zp[(size_t)(r + 8) * G4 + col] =
                    make_float2(acc[mi][ni][2], acc[mi][ni][3]);
            }

        grid_sync(bar_target);   // partials visible

        // ---- Phase B: reduce partials -> gates -> c/h ----
        if (upd) {
            #pragma unroll
            for (int e = 0; e < 2; ++e) {
                int idx = uidx[e];
                int b = idx >> 10;
                int n = idx & 1023;
                int zrow = b * G4 + n;

                float z[4];
                #pragma unroll
                for (int g = 0; g < 4; ++g) {
                    float v = zb[e][g];
                    #pragma unroll
                    for (int s = 0; s < KSPL; ++s)
                        v += __ldcg(&g_zp[s][zrow + g * Hsz]);
                    z[g] = v;
                }

                float ig = sigf(z[0]);
                float gg = fmaxf(z[1], 0.0f);        // relu cell-input activation
                float fg = sigf(z[2]);               // bias already includes +1
                float og = sigf(z[3]);

                float cn = fg * creg[e] + ig * gg;
                creg[e] = cn;
                float hn = og * fmaxf(cn, 0.0f);     // relu output activation

                __nv_bfloat16 hh = __float2bfloat16(hn);
                g_h_hi[idx] = hh;
                g_h_lo[idx] = __float2bfloat16(hn - __bfloat162float(hh));
                g_hout[((size_t)b * Tlen + t) * Hsz + n] = hn;
            }
        }

        grid_sync(bar_target);   // h visible before next step's GEMM
    }
}

// ---------------------------------------------------------------------------
// Final dense: out[B*T][128] = g_hout @ Wd + bd.
// ---------------------------------------------------------------------------
#define KC 32
__global__ __launch_bounds__(256) void dense_kernel(
    const float* __restrict__ Wd, const float* __restrict__ bd,
    float* __restrict__ out)
{
    __shared__ float a_s[64][KC + 1];
    __shared__ float w_s[KC][128];

    const int rb  = blockIdx.y * 64;
    const int tid = threadIdx.x;
    const int ty  = tid >> 5;
    const int tx  = tid & 31;
    const int r0  = ty * 8;
    const int c0  = tx * 4;

    float acc[8][4] = {};

    for (int k0 = 0; k0 < Hsz; k0 += KC) {
        #pragma unroll
        for (int i = 0; i < 8; ++i)
            a_s[i * 8 + ty][tx] = g_hout[(size_t)(rb + i * 8 + ty) * Hsz + k0 + tx];
        #pragma unroll
        for (int i = 0; i < 16; ++i) {
            int k = i * 2 + (tid >> 7);
            int c = tid & 127;
            w_s[k][c] = Wd[(size_t)(k0 + k) * Osz + c];
        }
        __syncthreads();

        #pragma unroll
        for (int k = 0; k < KC; ++k) {
            float4 wv = *(const float4*)&w_s[k][c0];
            #pragma unroll
            for (int i = 0; i < 8; ++i) {
                float a = a_s[r0 + i][k];
                acc[i][0] += a * wv.x;  acc[i][1] += a * wv.y;
                acc[i][2] += a * wv.z;  acc[i][3] += a * wv.w;
            }
        }
        __syncthreads();
    }

    float4 bv = *(const float4*)&bd[c0];
    #pragma unroll
    for (int i = 0; i < 8; ++i) {
        float4 o;
        o.x = acc[i][0] + bv.x;  o.y = acc[i][1] + bv.y;
        o.z = acc[i][2] + bv.z;  o.w = acc[i][3] + bv.w;
        *(float4*)&out[(size_t)(rb + r0 + i) * Osz + c0] = o;
    }
}

extern "C" void kernel_launch(void* const* d_in, const int* in_sizes, int n_in,
                              void* d_out, int out_size)
{
    const float* X  = (const float*)d_in[0];   // [B, T, I]
    const float* Wk = (const float*)d_in[1];   // [I+H, 4H]
    const float* b  = (const float*)d_in[2];   // [4H]
    const float* Wd = (const float*)d_in[3];   // [H, O]
    const float* bd = (const float*)d_in[4];   // [O]
    float* out = (float*)d_out;                // [B, T, O]
    (void)in_sizes; (void)n_in; (void)out_size;

    cudaFuncSetAttribute(lstm_persistent,
                         cudaFuncAttributeMaxDynamicSharedMemorySize, SMEM_BYTES);

    prep_w<<<dim3(KTOT / 32, G4 / 32), dim3(32, 8)>>>(Wk);
    prep_x<<<(Bsz * Tlen * Isz) / 256, 256>>>(X);
    init_state<<<(Bsz * Hsz + 255) / 256, 256>>>();
    lstm_persistent<<<NBLK, 256, SMEM_BYTES>>>(b);
    dense_kernel<<<dim3(1, (Bsz * Tlen) / 64), 256>>>(Wd, bd, out);
}

// round 10
// speedup vs baseline: 5.7683x; 1.0311x over previous
#include <cuda_runtime.h>
#include <cuda_bf16.h>
#include <cstdint>

// LSTM (relu activations, forget_bias=1) + per-timestep dense.
// B=64, T=512, I=128, H=1024, O=128. Gate order in Wk columns: i, j, f, o.
//
// R9: revert to the PROVEN bf16 3-term scheme (R8's fp16 2-term exploded:
// relu-LSTM amplifies h-quantization ~200x over 512 steps; need <=2^-14).
// New: ldmatrix.x4 fragment loads (96 LDSM vs 384 LDS.32 per warp per step
// -> tensor pipe no longer issue-starved), float2-vectorized update phase.

#define Bsz   64
#define Tlen  512
#define Isz   128
#define Hsz   1024
#define KTOT  1152
#define G4    4096
#define Osz   128

#define NBLK  144        // 16 col-tiles x 9 K-splits, co-resident on 148 SMs
#define KSPL  9
#define CTILE 256        // z-columns per block
#define KP    136        // padded k-stride (bf16) -> conflict-free ldmatrix
#define W_PLANE (CTILE * KP)   /* 34816 elems */
#define A_PLANE (64 * KP)      /*  8704 elems */
#define SMEM_BYTES ((2 * W_PLANE + 2 * A_PLANE) * 2)   /* 174080 B */

// ---- device-global scratch (allocation-free) ----
__device__ float          g_zp[KSPL][Bsz * G4];               // K-split partials
__device__ __nv_bfloat16  g_h_hi[Bsz * Hsz];
__device__ __nv_bfloat16  g_h_lo[Bsz * Hsz];
__device__ __nv_bfloat16  g_wT_hi[(size_t)G4 * KTOT];         // WkT[n][k] hi
__device__ __nv_bfloat16  g_wT_lo[(size_t)G4 * KTOT];         // WkT[n][k] lo
__device__ __nv_bfloat16  g_x_hi[Bsz * Tlen * Isz];
__device__ __nv_bfloat16  g_x_lo[Bsz * Tlen * Isz];
__device__ float          g_hout[(size_t)Bsz * Tlen * Hsz];   // 128 MB
__device__ unsigned       g_bar;

__device__ __forceinline__ float sigf(float x) { return 1.0f / (1.0f + __expf(-x)); }

// ---------------------------------------------------------------------------
// One-time preprocessing
// ---------------------------------------------------------------------------
__global__ void prep_w(const float* __restrict__ Wk) {
    __shared__ float tile[32][33];
    const int kb0 = blockIdx.x * 32;
    const int nb0 = blockIdx.y * 32;
    const int tx = threadIdx.x, ty = threadIdx.y;   // 32 x 8
    #pragma unroll
    for (int i = 0; i < 32; i += 8)
        tile[ty + i][tx] = Wk[(size_t)(kb0 + ty + i) * G4 + nb0 + tx];
    __syncthreads();
    #pragma unroll
    for (int i = 0; i < 32; i += 8) {
        int n = nb0 + ty + i, k = kb0 + tx;
        float v = tile[tx][ty + i];
        __nv_bfloat16 h = __float2bfloat16(v);
        size_t o = (size_t)n * KTOT + k;
        g_wT_hi[o] = h;
        g_wT_lo[o] = __float2bfloat16(v - __bfloat162float(h));
    }
}

__global__ void prep_x(const float* __restrict__ X) {
    int idx = blockIdx.x * 256 + threadIdx.x;
    float v = X[idx];
    __nv_bfloat16 h = __float2bfloat16(v);
    g_x_hi[idx] = h;
    g_x_lo[idx] = __float2bfloat16(v - __bfloat162float(h));
}

__global__ void init_state() {
    int idx = blockIdx.x * blockDim.x + threadIdx.x;
    if (idx < Bsz * Hsz) {
        g_h_hi[idx] = __float2bfloat16(0.0f);
        g_h_lo[idx] = __float2bfloat16(0.0f);
    }
    if (idx == 0) g_bar = 0u;
}

__device__ __forceinline__ void mma16816(float* d, const uint32_t* a, const uint32_t* b) {
    asm volatile(
        "mma.sync.aligned.m16n8k16.row.col.f32.bf16.bf16.f32 "
        "{%0,%1,%2,%3}, {%4,%5,%6,%7}, {%8,%9}, {%0,%1,%2,%3};"
        : "+f"(d[0]), "+f"(d[1]), "+f"(d[2]), "+f"(d[3])
        : "r"(a[0]), "r"(a[1]), "r"(a[2]), "r"(a[3]), "r"(b[0]), "r"(b[1]));
}

__device__ __forceinline__ void ldsm4(uint32_t* r, uint32_t addr) {
    asm volatile("ldmatrix.sync.aligned.m8n8.x4.shared.b16 {%0,%1,%2,%3}, [%4];"
        : "=r"(r[0]), "=r"(r[1]), "=r"(r[2]), "=r"(r[3]) : "r"(addr));
}

// Flush-free grid barrier (proven in R7): no membar.gl -> no CCTL.IVALL.
// Mutable cross-SM data is read via __ldcg, so this stays coherent.
__device__ __forceinline__ void grid_sync(unsigned& target) {
    __syncthreads();
    target += NBLK;
    if (threadIdx.x == 0) {
        asm volatile("red.release.gpu.add.u32 [%0], %1;" :: "l"(&g_bar), "r"(1u) : "memory");
        unsigned v;
        do {
            asm volatile("ld.acquire.gpu.u32 %0, [%1];" : "=r"(v) : "l"(&g_bar) : "memory");
        } while (v < target);
    }
    __syncthreads();
}

// ---------------------------------------------------------------------------
// Persistent kernel: 144 blocks x 256 threads, 170 KB dynamic smem.
// Block (colb, ks): z-cols [colb*256,+256), K-slice [ks*128,+128) of 1152.
// smem layout: [w_hi][w_lo][a_hi][a_lo], all rows strided KP=136 bf16.
// ---------------------------------------------------------------------------
__global__ __launch_bounds__(256, 1) void lstm_persistent(const float* __restrict__ bias)
{
    extern __shared__ __align__(16) uint16_t sm[];
    uint16_t* __restrict__ w_sm = sm;                  // 2 planes
    uint16_t* __restrict__ a_sm = sm + 2 * W_PLANE;    // 2 planes

    const int bid  = blockIdx.x;
    const int colb = bid / KSPL;
    const int ks   = bid - colb * KSPL;
    const int cb   = colb * CTILE;
    const int kb   = ks * 128;          // within 1152 (ks=0 -> X slice)

    const int tid  = threadIdx.x;
    const int w    = tid >> 5;
    const int lane = tid & 31;
    const int gq   = lane >> 2;         // 0..7
    const int qq   = lane & 3;          // 0..3

    // ---- one-time: weight slice (hi+lo) -> smem ----
    {
        const uint4* __restrict__ whi = (const uint4*)g_wT_hi;   // [n][144] uint4
        const uint4* __restrict__ wlo = (const uint4*)g_wT_lo;
        #pragma unroll
        for (int i = 0; i < 32; ++i) {
            int idx   = i * 256 + tid;          // 0..8191
            int plane = idx >> 12;
            int rem   = idx & 4095;
            int n     = rem >> 4;
            int kq    = rem & 15;
            const uint4* src = plane ? wlo : whi;
            uint4 v = src[(size_t)(cb + n) * 144 + (kb >> 3) + kq];
            *(uint4*)&w_sm[plane * W_PLANE + n * KP + kq * 8] = v;
        }
    }

    // ---- per-lane ldmatrix base addresses (byte addresses in shared space) --
    const uint32_t sm_u32 = (uint32_t)__cvta_generic_to_shared(sm);
    const int g   = lane >> 3;          // 8x8 tile index within x4
    const int rin = lane & 7;
    // W x4 = {bh[k], bh[k+8], bl[k], bl[k+8]} for one ni (n rows = w*32+ni*8+rin)
    const uint32_t w_addr0 = sm_u32 +
        ((g >> 1) * W_PLANE + (w * 32 + rin) * KP + (g & 1) * 8) * 2;
    // A x4 = {a0(r,k), a1(r+8,k), a2(r,k+8), a3(r+8,k+8)}; rows = mi*16+(g&1)*8+rin
    const uint32_t a_addr0 = sm_u32 +
        (2 * W_PLANE + ((g & 1) * 8 + rin) * KP + (g >> 1) * 8) * 2;

    // Phase-B ownership: block bid<128 owns batch row bb, n-pair columns.
    const bool upd = (bid < 128);
    const int  bb  = bid >> 1;
    const int  nb  = (bid & 1) * 512 + tid * 2;    // n, n+1
    float2 creg = make_float2(0.0f, 0.0f);
    float2 zb2[4];
    if (upd) {
        #pragma unroll
        for (int gg = 0; gg < 4; ++gg) {
            zb2[gg].x = bias[gg * Hsz + nb];
            zb2[gg].y = bias[gg * Hsz + nb + 1];
        }
        zb2[2].x += 1.0f;  zb2[2].y += 1.0f;       // TF forget_bias = 1
    }

    const uint4* __restrict__ xhi = (const uint4*)g_x_hi;   // [(b*T+t)][16]
    const uint4* __restrict__ xlo = (const uint4*)g_x_lo;
    const uint4* __restrict__ hhi = (const uint4*)g_h_hi;   // [b][128]
    const uint4* __restrict__ hlo = (const uint4*)g_h_lo;

    float* __restrict__ zp = g_zp[ks];
    unsigned bar_target = 0;

    for (int t = 0; t < Tlen; ++t) {
        // ---- stage A tile (64 rows x 128 k, hi+lo bf16 planes) ----
        #pragma unroll
        for (int i = 0; i < 8; ++i) {
            int idx   = i * 256 + tid;          // 0..2047
            int plane = idx >> 10;
            int rem   = idx & 1023;
            int row   = rem >> 4;
            int kq    = rem & 15;
            uint4 v;
            if (ks == 0) {
                const uint4* src = plane ? xlo : xhi;
                v = src[((size_t)row * Tlen + t) * 16 + kq];
            } else {
                const uint4* src = plane ? hlo : hhi;
                v = __ldcg(&src[(size_t)row * 128 + ((kb - Isz) >> 3) + kq]);
            }
            *(uint4*)&a_sm[plane * A_PLANE + row * KP + kq * 8] = v;
        }
        __syncthreads();

        // ---- MMA: 64 x 256 x 128, 3 hi/lo terms, ldmatrix-fed ----
        float acc[4][4][4] = {};
        #pragma unroll
        for (int kk = 0; kk < 128; kk += 16) {
            uint32_t bh[4][2], bl[4][2];
            #pragma unroll
            for (int ni = 0; ni < 4; ++ni) {
                uint32_t r[4];
                ldsm4(r, w_addr0 + (ni * 8 * KP + kk) * 2);
                bh[ni][0] = r[0];  bh[ni][1] = r[1];
                bl[ni][0] = r[2];  bl[ni][1] = r[3];
            }
            #pragma unroll
            for (int mi = 0; mi < 4; ++mi) {
                uint32_t ah[4], al[4];
                ldsm4(ah, a_addr0 + (mi * 16 * KP + kk) * 2);
                ldsm4(al, a_addr0 + A_PLANE * 2 + (mi * 16 * KP + kk) * 2);
                #pragma unroll
                for (int ni = 0; ni < 4; ++ni) {
                    mma16816(acc[mi][ni], ah, bh[ni]);   // hi*hi
                    mma16816(acc[mi][ni], ah, bl[ni]);   // hi*lo
                    mma16816(acc[mi][ni], al, bh[ni]);   // lo*hi
                }
            }
        }
        __syncthreads();   // a_sm reuse safety for next step's staging

        // ---- write z partials ----
        #pragma unroll
        for (int mi = 0; mi < 4; ++mi)
            #pragma unroll
            for (int ni = 0; ni < 4; ++ni) {
                int r   = mi * 16 + gq;
                int col = cb + w * 32 + ni * 8 + qq * 2;
                *(float2*)&zp[(size_t)r * G4 + col] =
                    make_float2(acc[mi][ni][0], acc[mi][ni][1]);
                *(float2*)&zp[(size_t)(r + 8) * G4 + col] =
                    make_float2(acc[mi][ni][2], acc[mi][ni][3]);
            }

        grid_sync(bar_target);   // partials visible

        // ---- Phase B: reduce partials -> gates -> c/h (float2 lanes) ----
        if (upd) {
            const int zrow = bb * G4 + nb;
            float2 z[4];
            #pragma unroll
            for (int gg = 0; gg < 4; ++gg) {
                float2 v = zb2[gg];
                #pragma unroll
                for (int s = 0; s < KSPL; ++s) {
                    float2 p = __ldcg((const float2*)&g_zp[s][zrow + gg * Hsz]);
                    v.x += p.x;  v.y += p.y;
                }
                z[gg] = v;
            }

            float2 hn;
            {
                float ig = sigf(z[0].x);
                float gg = fmaxf(z[1].x, 0.0f);      // relu cell-input activation
                float fg = sigf(z[2].x);             // bias already includes +1
                float og = sigf(z[3].x);
                float cn = fg * creg.x + ig * gg;
                creg.x = cn;
                hn.x = og * fmaxf(cn, 0.0f);         // relu output activation
            }
            {
                float ig = sigf(z[0].y);
                float gg = fmaxf(z[1].y, 0.0f);
                float fg = sigf(z[2].y);
                float og = sigf(z[3].y);
                float cn = fg * creg.y + ig * gg;
                creg.y = cn;
                hn.y = og * fmaxf(cn, 0.0f);
            }

            // bf16 hi/lo h stores (packed pairs) + fp32 history
            __nv_bfloat16 hx = __float2bfloat16(hn.x);
            __nv_bfloat16 hy = __float2bfloat16(hn.y);
            __nv_bfloat162 hip; hip.x = hx; hip.y = hy;
            __nv_bfloat162 lop;
            lop.x = __float2bfloat16(hn.x - __bfloat162float(hx));
            lop.y = __float2bfloat16(hn.y - __bfloat162float(hy));
            int hw = (bb * Hsz + nb) >> 1;
            ((uint32_t*)g_h_hi)[hw] = *(uint32_t*)&hip;
            ((uint32_t*)g_h_lo)[hw] = *(uint32_t*)&lop;
            *(float2*)&g_hout[((size_t)bb * Tlen + t) * Hsz + nb] = hn;
        }

        grid_sync(bar_target);   // h visible before next step's GEMM
    }
}

// ---------------------------------------------------------------------------
// Final dense: out[B*T][128] = g_hout @ Wd + bd.
// ---------------------------------------------------------------------------
#define KC 32
__global__ __launch_bounds__(256) void dense_kernel(
    const float* __restrict__ Wd, const float* __restrict__ bd,
    float* __restrict__ out)
{
    __shared__ float a_s[64][KC + 1];
    __shared__ float w_s[KC][128];

    const int rb  = blockIdx.y * 64;
    const int tid = threadIdx.x;
    const int ty  = tid >> 5;
    const int tx  = tid & 31;
    const int r0  = ty * 8;
    const int c0  = tx * 4;

    float acc[8][4] = {};

    for (int k0 = 0; k0 < Hsz; k0 += KC) {
        #pragma unroll
        for (int i = 0; i < 8; ++i)
            a_s[i * 8 + ty][tx] = g_hout[(size_t)(rb + i * 8 + ty) * Hsz + k0 + tx];
        #pragma unroll
        for (int i = 0; i < 16; ++i) {
            int k = i * 2 + (tid >> 7);
            int c = tid & 127;
            w_s[k][c] = Wd[(size_t)(k0 + k) * Osz + c];
        }
        __syncthreads();

        #pragma unroll
        for (int k = 0; k < KC; ++k) {
            float4 wv = *(const float4*)&w_s[k][c0];
            #pragma unroll
            for (int i = 0; i < 8; ++i) {
                float a = a_s[r0 + i][k];
                acc[i][0] += a * wv.x;  acc[i][1] += a * wv.y;
                acc[i][2] += a * wv.z;  acc[i][3] += a * wv.w;
            }
        }
        __syncthreads();
    }

    float4 bv = *(const float4*)&bd[c0];
    #pragma unroll
    for (int i = 0; i < 8; ++i) {
        float4 o;
        o.x = acc[i][0] + bv.x;  o.y = acc[i][1] + bv.y;
        o.z = acc[i][2] + bv.z;  o.w = acc[i][3] + bv.w;
        *(float4*)&out[(size_t)(rb + r0 + i) * Osz + c0] = o;
    }
}

extern "C" void kernel_launch(void* const* d_in, const int* in_sizes, int n_in,
                              void* d_out, int out_size)
{
    const float* X  = (const float*)d_in[0];   // [B, T, I]
    const float* Wk = (const float*)d_in[1];   // [I+H, 4H]
    const float* b  = (const float*)d_in[2];   // [4H]
    const float* Wd = (const float*)d_in[3];   // [H, O]
    const float* bd = (const float*)d_in[4];   // [O]
    float* out = (float*)d_out;                // [B, T, O]
    (void)in_sizes; (void)n_in; (void)out_size;

    cudaFuncSetAttribute(lstm_persistent,
                         cudaFuncAttributeMaxDynamicSharedMemorySize, SMEM_BYTES);

    prep_w<<<dim3(KTOT / 32, G4 / 32), dim3(32, 8)>>>(Wk);
    prep_x<<<(Bsz * Tlen * Isz) / 256, 256>>>(X);
    init_state<<<(Bsz * Hsz + 255) / 256, 256>>>();
    lstm_persistent<<<NBLK, 256, SMEM_BYTES>>>(b);
    dense_kernel<<<dim3(1, (Bsz * Tlen) / 64), 256>>>(Wd, bd, out);
}